// round 1
// baseline (speedup 1.0000x reference)
#include <cuda_runtime.h>

#define BATCH 32
#define CIN   256
#define HW    3136          // 56*56
#define HWH   1568          // HW/2
#define CR    8
#define NPIX  (BATCH*HW)    // 100352
#define NPAIR (NPIX/2)      // 50176
#define COUT  44            // 8 + 36

// ---- device scratch (no allocations allowed) ----
__device__ unsigned long long g_wdup[CIN*CR]; // [ci][c], each = {w,w} packed f32x2
__device__ float              g_bias[CR];
__device__ float              g_wdw[CR*9];    // depthwise weights * scale
__device__ float              g_z[NPIX*CR];   // relu(bn(conv1x1)) : [(b*8+c)*HW + p]

// ---- packed f32x2 fma ----
__device__ __forceinline__ unsigned long long fma2(unsigned long long a,
                                                   unsigned long long b,
                                                   unsigned long long c) {
    unsigned long long d;
    asm("fma.rn.f32x2 %0, %1, %2, %3;" : "=l"(d) : "l"(a), "l"(b), "l"(c));
    return d;
}
__device__ __forceinline__ unsigned long long pack2(float lo, float hi) {
    float2 v = make_float2(lo, hi);
    unsigned long long r;
    asm("mov.b64 %0, {%1, %2};" : "=l"(r) : "f"(v.x), "f"(v.y));
    return r;
}
__device__ __forceinline__ float2 unpack2(unsigned long long v) {
    float2 r;
    asm("mov.b64 {%0, %1}, %2;" : "=f"(r.x), "=f"(r.y) : "l"(v));
    return r;
}

// ============================================================
// Prep: fold BN into 1x1 weights (+bias), fold scale into dw weights
// ============================================================
__global__ void prep_k(const float* __restrict__ wr,
                       const float* __restrict__ gamma,
                       const float* __restrict__ beta,
                       const float* __restrict__ mean,
                       const float* __restrict__ var,
                       const float* __restrict__ wdw,
                       const float* __restrict__ scale) {
    int t = threadIdx.x;
    for (int i = t; i < CIN*CR; i += blockDim.x) {
        int ci = i >> 3;
        int c  = i & 7;
        float inv = gamma[c] * rsqrtf(var[c] + 1e-5f);
        float w   = wr[c*CIN + ci] * inv;
        g_wdup[i] = pack2(w, w);
    }
    if (t < CR) {
        float inv = gamma[t] * rsqrtf(var[t] + 1e-5f);
        g_bias[t] = beta[t] - mean[t] * inv;
    }
    if (t < CR*9) {
        g_wdw[t] = wdw[t] * scale[t/9];
    }
}

// ============================================================
// 1x1 conv + BN + ReLU, packed f32x2 (2 pixels per thread)
// grid = 196 blocks * 256 threads == NPAIR exactly
// ============================================================
__global__ void __launch_bounds__(256) conv1x1_k(const float* __restrict__ x) {
    __shared__ unsigned long long sw[CIN*CR];  // 16 KB
    __shared__ float sbias[CR];

    {   // stage folded weights into smem (1024 float4)
        const float4* src = reinterpret_cast<const float4*>(g_wdup);
        float4* dst = reinterpret_cast<float4*>(sw);
        #pragma unroll
        for (int i = threadIdx.x; i < (CIN*CR*2)/4; i += 256) dst[i] = src[i];
        if (threadIdx.x < CR) sbias[threadIdx.x] = g_bias[threadIdx.x];
    }
    __syncthreads();

    int pp = blockIdx.x * 256 + threadIdx.x;      // pair index, exact coverage
    int b  = pp / HWH;
    int pi = pp % HWH;

    const unsigned long long* xp =
        reinterpret_cast<const unsigned long long*>(x) + (size_t)b*CIN*HWH + pi;

    unsigned long long acc[CR];
    #pragma unroll
    for (int c = 0; c < CR; c++) acc[c] = pack2(sbias[c], sbias[c]);

    #pragma unroll 1
    for (int ci = 0; ci < CIN; ci += 8) {
        unsigned long long xv[8];
        #pragma unroll
        for (int u = 0; u < 8; u++) xv[u] = xp[(size_t)(ci+u)*HWH];
        #pragma unroll
        for (int u = 0; u < 8; u++) {
            const unsigned long long* wrow = &sw[(ci+u)*CR];
            #pragma unroll
            for (int c = 0; c < CR; c++) acc[c] = fma2(wrow[c], xv[u], acc[c]);
        }
    }

    unsigned long long* zp =
        reinterpret_cast<unsigned long long*>(g_z) + (size_t)b*CR*HWH + pi;
    #pragma unroll
    for (int c = 0; c < CR; c++) {
        float2 v = unpack2(acc[c]);
        v.x = fmaxf(v.x, 0.f);
        v.y = fmaxf(v.y, 0.f);
        zp[(size_t)c*HWH] = pack2(v.x, v.y);
    }
}

// ============================================================
// Depthwise 3x3 (*scale) + channel L2-norms + pairwise products
// grid = 392 blocks * 256 threads == NPIX exactly
// ============================================================
__global__ void __launch_bounds__(256) twist_k(float* __restrict__ out) {
    __shared__ float swd[CR*9];
    if (threadIdx.x < CR*9) swd[threadIdx.x] = g_wdw[threadIdx.x];
    __syncthreads();

    int idx = blockIdx.x * 256 + threadIdx.x;
    int b = idx / HW;
    int p = idx % HW;
    int y  = p / 56;
    int xw = p % 56;

    const float* zb = g_z + (size_t)b*CR*HW;

    float zc[CR], t[CR];
    #pragma unroll
    for (int c = 0; c < CR; c++) {
        zc[c] = __ldg(zb + c*HW + p);
        t[c]  = 0.f;
    }

    #pragma unroll
    for (int dy = -1; dy <= 1; dy++) {
        int yy = y + dy;
        if ((unsigned)yy >= 56u) continue;
        #pragma unroll
        for (int dx = -1; dx <= 1; dx++) {
            int xx = xw + dx;
            if ((unsigned)xx >= 56u) continue;
            int q = yy*56 + xx;
            int k = (dy+1)*3 + (dx+1);
            #pragma unroll
            for (int c = 0; c < CR; c++)
                t[c] = fmaf(__ldg(zb + c*HW + q), swd[c*9 + k], t[c]);
        }
    }

    float s2z = 0.f, s2t = 0.f;
    #pragma unroll
    for (int c = 0; c < CR; c++) { s2z = fmaf(zc[c], zc[c], s2z); s2t = fmaf(t[c], t[c], s2t); }
    float iz = 1.0f / fmaxf(sqrtf(s2z), 1e-6f);
    float it = 1.0f / fmaxf(sqrtf(s2t), 1e-6f);

    float zn[CR], tn[CR];
    #pragma unroll
    for (int c = 0; c < CR; c++) { zn[c] = zc[c]*iz; tn[c] = t[c]*it; }

    float* ob = out + (size_t)b*COUT*HW + p;
    #pragma unroll
    for (int c = 0; c < CR; c++) ob[(size_t)c*HW] = zn[c];

    int k = 8;
    #pragma unroll
    for (int i = 0; i < CR; i++) {
        #pragma unroll
        for (int j = i; j < CR; j++) {
            ob[(size_t)k*HW] = zn[i]*tn[j];
            k++;
        }
    }
}

// ============================================================
extern "C" void kernel_launch(void* const* d_in, const int* in_sizes, int n_in,
                              void* d_out, int out_size) {
    const float* x     = (const float*)d_in[0];
    const float* wr    = (const float*)d_in[1];
    const float* gamma = (const float*)d_in[2];
    const float* beta  = (const float*)d_in[3];
    const float* mean  = (const float*)d_in[4];
    const float* var   = (const float*)d_in[5];
    const float* wdw   = (const float*)d_in[6];
    const float* scale = (const float*)d_in[7];
    float* out = (float*)d_out;

    prep_k<<<1, 256>>>(wr, gamma, beta, mean, var, wdw, scale);
    conv1x1_k<<<NPAIR/256, 256>>>(x);
    twist_k<<<NPIX/256, 256>>>(out);
}

// round 2
// speedup vs baseline: 1.2702x; 1.2702x over previous
#include <cuda_runtime.h>

#define BATCH 32
#define CIN   256
#define HW    3136          // 56*56
#define HWH   1568          // HW/2
#define CR    8
#define NPIX  (BATCH*HW)    // 100352
#define NPAIR (NPIX/2)      // 50176
#define COUT  44            // 8 + 36

// z buffer, pixel-major: [b][p][c], 32B per pixel record
__device__ float g_z[NPIX*CR];

// ---- packed f32x2 helpers ----
__device__ __forceinline__ unsigned long long fma2(unsigned long long a,
                                                   unsigned long long b,
                                                   unsigned long long c) {
    unsigned long long d;
    asm("fma.rn.f32x2 %0, %1, %2, %3;" : "=l"(d) : "l"(a), "l"(b), "l"(c));
    return d;
}
__device__ __forceinline__ unsigned long long pack2(float lo, float hi) {
    unsigned long long r;
    asm("mov.b64 %0, {%1, %2};" : "=l"(r) : "f"(lo), "f"(hi));
    return r;
}
__device__ __forceinline__ float2 unpack2(unsigned long long v) {
    float2 r;
    asm("mov.b64 {%0, %1}, %2;" : "=f"(r.x), "=f"(r.y) : "l"(v));
    return r;
}

// ============================================================
// 1x1 conv + BN(folded inline) + ReLU, packed f32x2, 2 px/thread
// grid = 392 blocks * 128 threads == NPAIR exactly
// ============================================================
__global__ void __launch_bounds__(128) conv1x1_k(const float* __restrict__ x,
                                                 const float* __restrict__ wr,
                                                 const float* __restrict__ gamma,
                                                 const float* __restrict__ beta,
                                                 const float* __restrict__ mean,
                                                 const float* __restrict__ var) {
    __shared__ unsigned long long sw[CIN*CR];  // 16 KB folded, duplicated weights
    __shared__ float sinv[CR], sbias[CR];

    if (threadIdx.x < CR) {
        int c = threadIdx.x;
        float inv = gamma[c] * rsqrtf(var[c] + 1e-5f);
        sinv[c]  = inv;
        sbias[c] = beta[c] - mean[c] * inv;
    }
    __syncthreads();
    #pragma unroll
    for (int i = threadIdx.x; i < CIN*CR; i += 128) {
        int ci = i >> 3;
        int c  = i & 7;
        float w = wr[c*CIN + ci] * sinv[c];
        sw[i] = pack2(w, w);
    }
    __syncthreads();

    int pp = blockIdx.x * 128 + threadIdx.x;   // pair index, exact coverage
    int b  = pp / HWH;
    int pi = pp % HWH;

    const unsigned long long* xp =
        reinterpret_cast<const unsigned long long*>(x) + (size_t)b*CIN*HWH + pi;

    unsigned long long acc[CR];
    #pragma unroll
    for (int c = 0; c < CR; c++) acc[c] = pack2(sbias[c], sbias[c]);

    #pragma unroll 1
    for (int ci = 0; ci < CIN; ci += 16) {
        unsigned long long xv[16];
        #pragma unroll
        for (int u = 0; u < 16; u++) xv[u] = __ldg(&xp[(size_t)(ci+u)*HWH]);
        #pragma unroll
        for (int u = 0; u < 16; u++) {
            const unsigned long long* wrow = &sw[(ci+u)*CR];
            #pragma unroll
            for (int c = 0; c < CR; c++) acc[c] = fma2(wrow[c], xv[u], acc[c]);
        }
    }

    // epilogue: relu, transpose pair -> pixel-major records, 64B contiguous store
    float2 v[CR];
    #pragma unroll
    for (int c = 0; c < CR; c++) {
        v[c] = unpack2(acc[c]);
        v[c].x = fmaxf(v[c].x, 0.f);
        v[c].y = fmaxf(v[c].y, 0.f);
    }
    int p0 = 2*pi;                              // first pixel of the pair
    float4* zp = reinterpret_cast<float4*>(g_z) + ((size_t)b*HW + p0)*2;
    zp[0] = make_float4(v[0].x, v[1].x, v[2].x, v[3].x);
    zp[1] = make_float4(v[4].x, v[5].x, v[6].x, v[7].x);
    zp[2] = make_float4(v[0].y, v[1].y, v[2].y, v[3].y);
    zp[3] = make_float4(v[4].y, v[5].y, v[6].y, v[7].y);
}

// ============================================================
// Depthwise 3x3 (scale folded inline) + L2-norms + pairwise products
// grid = 392 blocks * 256 threads == NPIX exactly
// ============================================================
__global__ void __launch_bounds__(256) twist_k(float* __restrict__ out,
                                               const float* __restrict__ wdw,
                                               const float* __restrict__ scale) {
    __shared__ float swd[CR*9];
    if (threadIdx.x < CR*9) swd[threadIdx.x] = wdw[threadIdx.x] * scale[threadIdx.x/9];
    __syncthreads();

    int idx = blockIdx.x * 256 + threadIdx.x;
    int b = idx / HW;
    int p = idx % HW;
    int y  = p / 56;
    int xw = p % 56;

    const float4* zb = reinterpret_cast<const float4*>(g_z) + (size_t)b*HW*2;

    float zc[CR], t[CR];
    {
        float4 a = __ldg(&zb[(size_t)p*2]);
        float4 c = __ldg(&zb[(size_t)p*2+1]);
        zc[0]=a.x; zc[1]=a.y; zc[2]=a.z; zc[3]=a.w;
        zc[4]=c.x; zc[5]=c.y; zc[6]=c.z; zc[7]=c.w;
    }
    #pragma unroll
    for (int c = 0; c < CR; c++) t[c] = 0.f;

    #pragma unroll
    for (int dy = -1; dy <= 1; dy++) {
        int yy = y + dy;
        if ((unsigned)yy >= 56u) continue;
        #pragma unroll
        for (int dx = -1; dx <= 1; dx++) {
            int xx = xw + dx;
            if ((unsigned)xx >= 56u) continue;
            int q = yy*56 + xx;
            int k = (dy+1)*3 + (dx+1);
            float4 a = __ldg(&zb[(size_t)q*2]);
            float4 c = __ldg(&zb[(size_t)q*2+1]);
            t[0] = fmaf(a.x, swd[0*9+k], t[0]);
            t[1] = fmaf(a.y, swd[1*9+k], t[1]);
            t[2] = fmaf(a.z, swd[2*9+k], t[2]);
            t[3] = fmaf(a.w, swd[3*9+k], t[3]);
            t[4] = fmaf(c.x, swd[4*9+k], t[4]);
            t[5] = fmaf(c.y, swd[5*9+k], t[5]);
            t[6] = fmaf(c.z, swd[6*9+k], t[6]);
            t[7] = fmaf(c.w, swd[7*9+k], t[7]);
        }
    }

    float s2z = 0.f, s2t = 0.f;
    #pragma unroll
    for (int c = 0; c < CR; c++) { s2z = fmaf(zc[c], zc[c], s2z); s2t = fmaf(t[c], t[c], s2t); }
    float iz = 1.0f / fmaxf(sqrtf(s2z), 1e-6f);
    float it = 1.0f / fmaxf(sqrtf(s2t), 1e-6f);

    float zn[CR], tn[CR];
    #pragma unroll
    for (int c = 0; c < CR; c++) { zn[c] = zc[c]*iz; tn[c] = t[c]*it; }

    float* ob = out + (size_t)b*COUT*HW + p;
    #pragma unroll
    for (int c = 0; c < CR; c++) ob[(size_t)c*HW] = zn[c];

    int k = 8;
    #pragma unroll
    for (int i = 0; i < CR; i++) {
        #pragma unroll
        for (int j = i; j < CR; j++) {
            ob[(size_t)k*HW] = zn[i]*tn[j];
            k++;
        }
    }
}

// ============================================================
extern "C" void kernel_launch(void* const* d_in, const int* in_sizes, int n_in,
                              void* d_out, int out_size) {
    const float* x     = (const float*)d_in[0];
    const float* wr    = (const float*)d_in[1];
    const float* gamma = (const float*)d_in[2];
    const float* beta  = (const float*)d_in[3];
    const float* mean  = (const float*)d_in[4];
    const float* var   = (const float*)d_in[5];
    const float* wdw   = (const float*)d_in[6];
    const float* scale = (const float*)d_in[7];
    float* out = (float*)d_out;

    conv1x1_k<<<NPAIR/128, 128>>>(x, wr, gamma, beta, mean, var);
    twist_k<<<NPIX/256, 256>>>(out, wdw, scale);
}

// round 3
// speedup vs baseline: 1.4413x; 1.1348x over previous
#include <cuda_runtime.h>

#define BATCH 32
#define CIN   256
#define HW    3136          // 56*56
#define HWH   1568          // HW/2
#define CR    8
#define NPIX  (BATCH*HW)    // 100352
#define NPAIR (NPIX/2)      // 50176
#define COUT  44            // 8 + 36

#define KS    4             // K-splits per pixel-pair
#define CPK   (CIN/KS)      // 64 channels per split
#define PPB   64            // pixel-pairs per block (256 threads = 64 pairs * 4 splits)

// z buffer, pixel-major: [b][p][c], 32B per pixel record
__device__ float g_z[NPIX*CR];

typedef unsigned long long u64;

// ---- packed f32x2 helpers ----
__device__ __forceinline__ u64 fma2(u64 a, u64 b, u64 c) {
    u64 d;
    asm("fma.rn.f32x2 %0, %1, %2, %3;" : "=l"(d) : "l"(a), "l"(b), "l"(c));
    return d;
}
__device__ __forceinline__ u64 add2(u64 a, u64 b) {
    u64 d;
    asm("add.rn.f32x2 %0, %1, %2;" : "=l"(d) : "l"(a), "l"(b));
    return d;
}
__device__ __forceinline__ u64 pack2(float lo, float hi) {
    u64 r;
    asm("mov.b64 %0, {%1, %2};" : "=l"(r) : "f"(lo), "f"(hi));
    return r;
}
__device__ __forceinline__ float2 unpack2(u64 v) {
    float2 r;
    asm("mov.b64 {%0, %1}, %2;" : "=f"(r.x), "=f"(r.y) : "l"(v));
    return r;
}

// ============================================================
// 1x1 conv + BN(folded) + ReLU. K-split x4, f32x2, 2 px/thread.
// grid = NPAIR/PPB = 784 blocks * 256 threads
// ============================================================
__global__ void __launch_bounds__(256) conv1x1_k(const float* __restrict__ x,
                                                 const float* __restrict__ wr,
                                                 const float* __restrict__ gamma,
                                                 const float* __restrict__ beta,
                                                 const float* __restrict__ mean,
                                                 const float* __restrict__ var) {
    __shared__ u64   sw[CIN*CR];        // 16 KB folded duplicated weights
    __shared__ u64   sred[256*CR];      // 16 KB reduction buffer
    __shared__ float sinv[CR], sbias[CR];

    if (threadIdx.x < CR) {
        int c = threadIdx.x;
        float inv = gamma[c] * rsqrtf(var[c] + 1e-5f);
        sinv[c]  = inv;
        sbias[c] = beta[c] - mean[c] * inv;
    }
    __syncthreads();
    #pragma unroll
    for (int i = threadIdx.x; i < CIN*CR; i += 256) {
        int ci = i >> 3;
        int c  = i & 7;
        float w = wr[c*CIN + ci] * sinv[c];
        sw[i] = pack2(w, w);
    }
    __syncthreads();

    int lp = threadIdx.x & (PPB-1);      // pair within block
    int ks = threadIdx.x >> 6;           // k-split 0..3
    int pp = blockIdx.x * PPB + lp;      // global pair index, exact coverage
    int b  = pp / HWH;
    int pi = pp % HWH;

    const u64* xp = reinterpret_cast<const u64*>(x)
                  + (size_t)b*CIN*HWH + (size_t)(ks*CPK)*HWH + pi;

    u64 acc[CR];
    #pragma unroll
    for (int c = 0; c < CR; c++) acc[c] = 0ull;

    #pragma unroll 1
    for (int ci = 0; ci < CPK; ci += 8) {
        u64 xv[8];
        #pragma unroll
        for (int u = 0; u < 8; u++) xv[u] = __ldg(&xp[(size_t)(ci+u)*HWH]);
        #pragma unroll
        for (int u = 0; u < 8; u++) {
            const ulonglong2* wrow =
                reinterpret_cast<const ulonglong2*>(&sw[(ks*CPK + ci + u)*CR]);
            ulonglong2 w01 = wrow[0], w23 = wrow[1], w45 = wrow[2], w67 = wrow[3];
            acc[0] = fma2(w01.x, xv[u], acc[0]);
            acc[1] = fma2(w01.y, xv[u], acc[1]);
            acc[2] = fma2(w23.x, xv[u], acc[2]);
            acc[3] = fma2(w23.y, xv[u], acc[3]);
            acc[4] = fma2(w45.x, xv[u], acc[4]);
            acc[5] = fma2(w45.y, xv[u], acc[5]);
            acc[6] = fma2(w67.x, xv[u], acc[6]);
            acc[7] = fma2(w67.y, xv[u], acc[7]);
        }
    }

    // stash partials
    u64* my = &sred[(size_t)threadIdx.x*CR];
    #pragma unroll
    for (int c = 0; c < CR; c++) my[c] = acc[c];
    __syncthreads();

    // threads 0..63 reduce 4 splits, add bias, relu, store pixel-major
    if (threadIdx.x < PPB) {
        u64 fin[CR];
        #pragma unroll
        for (int c = 0; c < CR; c++) {
            u64 s = sred[(size_t)lp*CR + c];
            s = add2(s, sred[(size_t)(lp +  64)*CR + c]);
            s = add2(s, sred[(size_t)(lp + 128)*CR + c]);
            s = add2(s, sred[(size_t)(lp + 192)*CR + c]);
            fin[c] = s;
        }
        float2 v[CR];
        #pragma unroll
        for (int c = 0; c < CR; c++) {
            v[c] = unpack2(fin[c]);
            v[c].x = fmaxf(v[c].x + sbias[c], 0.f);
            v[c].y = fmaxf(v[c].y + sbias[c], 0.f);
        }
        int p0 = 2*pi;
        float4* zp = reinterpret_cast<float4*>(g_z) + ((size_t)b*HW + p0)*2;
        zp[0] = make_float4(v[0].x, v[1].x, v[2].x, v[3].x);
        zp[1] = make_float4(v[4].x, v[5].x, v[6].x, v[7].x);
        zp[2] = make_float4(v[0].y, v[1].y, v[2].y, v[3].y);
        zp[3] = make_float4(v[4].y, v[5].y, v[6].y, v[7].y);
    }
}

// ============================================================
// Depthwise 3x3 (scale folded) + L2-norms + pairwise products.
// Branch-free clamped taps -> all 18 LDG.128 batched up front.
// grid = 392 blocks * 256 threads == NPIX exactly
// ============================================================
__global__ void __launch_bounds__(256) twist_k(float* __restrict__ out,
                                               const float* __restrict__ wdw,
                                               const float* __restrict__ scale) {
    __shared__ float swd[CR*9];
    if (threadIdx.x < CR*9) swd[threadIdx.x] = wdw[threadIdx.x] * scale[threadIdx.x/9];
    __syncthreads();

    int idx = blockIdx.x * 256 + threadIdx.x;
    int b = idx / HW;
    int p = idx % HW;
    int y  = p / 56;
    int xw = p % 56;

    const float4* zb = reinterpret_cast<const float4*>(g_z) + (size_t)b*HW*2;

    // all 9 taps: clamped addresses + 0/1 mask, loads batched
    float4 av[9], cv[9];
    float  mk[9];
    #pragma unroll
    for (int k = 0; k < 9; k++) {
        int dy = k/3 - 1, dx = k%3 - 1;
        int yy = y + dy, xx = xw + dx;
        bool valid = ((unsigned)yy < 56u) && ((unsigned)xx < 56u);
        int yc = min(max(yy, 0), 55);
        int xc = min(max(xx, 0), 55);
        int q  = yc*56 + xc;
        av[k] = __ldg(&zb[(size_t)q*2]);
        cv[k] = __ldg(&zb[(size_t)q*2 + 1]);
        mk[k] = valid ? 1.f : 0.f;
    }

    float zc[CR];
    zc[0]=av[4].x; zc[1]=av[4].y; zc[2]=av[4].z; zc[3]=av[4].w;
    zc[4]=cv[4].x; zc[5]=cv[4].y; zc[6]=cv[4].z; zc[7]=cv[4].w;

    float t[CR];
    #pragma unroll
    for (int c = 0; c < CR; c++) t[c] = 0.f;
    #pragma unroll
    for (int k = 0; k < 9; k++) {
        float m = mk[k];
        t[0] = fmaf(av[k].x * m, swd[0*9+k], t[0]);
        t[1] = fmaf(av[k].y * m, swd[1*9+k], t[1]);
        t[2] = fmaf(av[k].z * m, swd[2*9+k], t[2]);
        t[3] = fmaf(av[k].w * m, swd[3*9+k], t[3]);
        t[4] = fmaf(cv[k].x * m, swd[4*9+k], t[4]);
        t[5] = fmaf(cv[k].y * m, swd[5*9+k], t[5]);
        t[6] = fmaf(cv[k].z * m, swd[6*9+k], t[6]);
        t[7] = fmaf(cv[k].w * m, swd[7*9+k], t[7]);
    }

    float s2z = 0.f, s2t = 0.f;
    #pragma unroll
    for (int c = 0; c < CR; c++) { s2z = fmaf(zc[c], zc[c], s2z); s2t = fmaf(t[c], t[c], s2t); }
    float iz = 1.0f / fmaxf(sqrtf(s2z), 1e-6f);
    float it = 1.0f / fmaxf(sqrtf(s2t), 1e-6f);

    float zn[CR], tn[CR];
    #pragma unroll
    for (int c = 0; c < CR; c++) { zn[c] = zc[c]*iz; tn[c] = t[c]*it; }

    float* ob = out + (size_t)b*COUT*HW + p;
    #pragma unroll
    for (int c = 0; c < CR; c++) ob[(size_t)c*HW] = zn[c];

    int k = 8;
    #pragma unroll
    for (int i = 0; i < CR; i++) {
        #pragma unroll
        for (int j = i; j < CR; j++) {
            ob[(size_t)k*HW] = zn[i]*tn[j];
            k++;
        }
    }
}

// ============================================================
extern "C" void kernel_launch(void* const* d_in, const int* in_sizes, int n_in,
                              void* d_out, int out_size) {
    const float* x     = (const float*)d_in[0];
    const float* wr    = (const float*)d_in[1];
    const float* gamma = (const float*)d_in[2];
    const float* beta  = (const float*)d_in[3];
    const float* mean  = (const float*)d_in[4];
    const float* var   = (const float*)d_in[5];
    const float* wdw   = (const float*)d_in[6];
    const float* scale = (const float*)d_in[7];
    float* out = (float*)d_out;

    conv1x1_k<<<NPAIR/PPB, 256>>>(x, wr, gamma, beta, mean, var);
    twist_k<<<NPIX/256, 256>>>(out, wdw, scale);
}

// round 4
// speedup vs baseline: 1.6767x; 1.1633x over previous
#include <cuda_runtime.h>

#define BATCH 32
#define CIN   256
#define HW    3136          // 56*56
#define HWH   1568          // HW/2
#define CR    8
#define NPIX  (BATCH*HW)    // 100352
#define NPAIR (NPIX/2)      // 50176
#define COUT  44            // 8 + 36

#define KS    4             // K-splits per pixel-pair
#define CPK   (CIN/KS)      // 64 channels per split
#define PPB   64            // pixel-pairs per block (256 threads = 64 pairs * 4 splits)

// z buffer, pixel-major: [b][p][c], 32B per pixel record
__device__ float g_z[NPIX*CR];

typedef unsigned long long u64;

// ---- packed f32x2 helpers ----
__device__ __forceinline__ u64 fma2(u64 a, u64 b, u64 c) {
    u64 d;
    asm("fma.rn.f32x2 %0, %1, %2, %3;" : "=l"(d) : "l"(a), "l"(b), "l"(c));
    return d;
}
__device__ __forceinline__ u64 add2(u64 a, u64 b) {
    u64 d;
    asm("add.rn.f32x2 %0, %1, %2;" : "=l"(d) : "l"(a), "l"(b));
    return d;
}
__device__ __forceinline__ u64 pack2(float lo, float hi) {
    u64 r;
    asm("mov.b64 %0, {%1, %2};" : "=l"(r) : "f"(lo), "f"(hi));
    return r;
}
__device__ __forceinline__ float2 unpack2(u64 v) {
    float2 r;
    asm("mov.b64 {%0, %1}, %2;" : "=f"(r.x), "=f"(r.y) : "l"(v));
    return r;
}

// fma of 8 accumulators against one x value, weights via 4x LDS.128 broadcast
__device__ __forceinline__ void fma_step(u64* acc, const u64* swrow, u64 xv) {
    const ulonglong2* wrow = reinterpret_cast<const ulonglong2*>(swrow);
    ulonglong2 w01 = wrow[0], w23 = wrow[1], w45 = wrow[2], w67 = wrow[3];
    acc[0] = fma2(w01.x, xv, acc[0]);
    acc[1] = fma2(w01.y, xv, acc[1]);
    acc[2] = fma2(w23.x, xv, acc[2]);
    acc[3] = fma2(w23.y, xv, acc[3]);
    acc[4] = fma2(w45.x, xv, acc[4]);
    acc[5] = fma2(w45.y, xv, acc[5]);
    acc[6] = fma2(w67.x, xv, acc[6]);
    acc[7] = fma2(w67.y, xv, acc[7]);
}

// ============================================================
// 1x1 conv + BN(folded) + ReLU. K-split x4, f32x2, 2 px/thread,
// 2-stage software-pipelined loads (16 LDG.64 in flight).
// grid = NPAIR/PPB = 784 blocks * 256 threads
// ============================================================
__global__ void __launch_bounds__(256) conv1x1_k(const float* __restrict__ x,
                                                 const float* __restrict__ wr,
                                                 const float* __restrict__ gamma,
                                                 const float* __restrict__ beta,
                                                 const float* __restrict__ mean,
                                                 const float* __restrict__ var) {
    __shared__ u64   sw[CIN*CR];        // 16 KB folded duplicated weights
    __shared__ u64   sred[256*CR];      // 16 KB reduction buffer
    __shared__ float sinv[CR], sbias[CR];

    if (threadIdx.x < CR) {
        int c = threadIdx.x;
        float inv = gamma[c] * rsqrtf(var[c] + 1e-5f);
        sinv[c]  = inv;
        sbias[c] = beta[c] - mean[c] * inv;
    }
    __syncthreads();
    #pragma unroll
    for (int i = threadIdx.x; i < CIN*CR; i += 256) {
        int ci = i >> 3;
        int c  = i & 7;
        float w = wr[c*CIN + ci] * sinv[c];
        sw[i] = pack2(w, w);
    }
    __syncthreads();

    int lp = threadIdx.x & (PPB-1);      // pair within block
    int ks = threadIdx.x >> 6;           // k-split 0..3
    int pp = blockIdx.x * PPB + lp;      // global pair index, exact coverage
    int b  = pp / HWH;
    int pi = pp % HWH;

    const u64* xp = reinterpret_cast<const u64*>(x)
                  + (size_t)b*CIN*HWH + (size_t)(ks*CPK)*HWH + pi;
    const u64* swb = &sw[ks*CPK*CR];

    u64 acc[CR];
    #pragma unroll
    for (int c = 0; c < CR; c++) acc[c] = 0ull;

    u64 xa[8], xb[8];
    #pragma unroll
    for (int u = 0; u < 8; u++) xa[u] = __ldg(&xp[(size_t)u*HWH]);

    #pragma unroll 1
    for (int ci = 0; ci < CPK; ci += 16) {
        // stage B loads (independent of stage A compute) — issued first
        #pragma unroll
        for (int u = 0; u < 8; u++) xb[u] = __ldg(&xp[(size_t)(ci+8+u)*HWH]);
        // stage A compute
        #pragma unroll
        for (int u = 0; u < 8; u++) fma_step(acc, &swb[(ci+u)*CR], xa[u]);
        // stage A loads for next iteration
        if (ci + 16 < CPK) {
            #pragma unroll
            for (int u = 0; u < 8; u++) xa[u] = __ldg(&xp[(size_t)(ci+16+u)*HWH]);
        }
        // stage B compute
        #pragma unroll
        for (int u = 0; u < 8; u++) fma_step(acc, &swb[(ci+8+u)*CR], xb[u]);
    }

    // stash partials
    u64* my = &sred[(size_t)threadIdx.x*CR];
    #pragma unroll
    for (int c = 0; c < CR; c++) my[c] = acc[c];
    __syncthreads();

    // threads 0..63 reduce 4 splits, add bias, relu, store pixel-major
    if (threadIdx.x < PPB) {
        u64 fin[CR];
        #pragma unroll
        for (int c = 0; c < CR; c++) {
            u64 s = sred[(size_t)lp*CR + c];
            s = add2(s, sred[(size_t)(lp +  64)*CR + c]);
            s = add2(s, sred[(size_t)(lp + 128)*CR + c]);
            s = add2(s, sred[(size_t)(lp + 192)*CR + c]);
            fin[c] = s;
        }
        float2 v[CR];
        #pragma unroll
        for (int c = 0; c < CR; c++) {
            v[c] = unpack2(fin[c]);
            v[c].x = fmaxf(v[c].x + sbias[c], 0.f);
            v[c].y = fmaxf(v[c].y + sbias[c], 0.f);
        }
        int p0 = 2*pi;
        float4* zp = reinterpret_cast<float4*>(g_z) + ((size_t)b*HW + p0)*2;
        zp[0] = make_float4(v[0].x, v[1].x, v[2].x, v[3].x);
        zp[1] = make_float4(v[4].x, v[5].x, v[6].x, v[7].x);
        zp[2] = make_float4(v[0].y, v[1].y, v[2].y, v[3].y);
        zp[3] = make_float4(v[4].y, v[5].y, v[6].y, v[7].y);
    }
}

// ============================================================
// Depthwise 3x3 (scale folded) + L2-norms + pairwise products.
// Row-by-row taps (6 float4 live) to keep registers low.
// grid = 392 blocks * 256 threads == NPIX exactly
// ============================================================
__global__ void __launch_bounds__(256) twist_k(float* __restrict__ out,
                                               const float* __restrict__ wdw,
                                               const float* __restrict__ scale) {
    __shared__ float swd[CR*9];
    if (threadIdx.x < CR*9) swd[threadIdx.x] = wdw[threadIdx.x] * scale[threadIdx.x/9];
    __syncthreads();

    int idx = blockIdx.x * 256 + threadIdx.x;
    int b = idx / HW;
    int p = idx % HW;
    int y  = p / 56;
    int xw = p % 56;

    const float4* zb = reinterpret_cast<const float4*>(g_z) + (size_t)b*HW*2;

    float zc[CR], t[CR];
    #pragma unroll
    for (int c = 0; c < CR; c++) t[c] = 0.f;

    #pragma unroll
    for (int r = 0; r < 3; r++) {
        int yy = y + r - 1;
        bool rowv = (unsigned)yy < 56u;
        int yc = min(max(yy, 0), 55);

        // 3 taps of this row: batch 6 LDG.128 (L1/L2-hot)
        float4 av[3], cv[3];
        float  mk[3];
        #pragma unroll
        for (int d = 0; d < 3; d++) {
            int xx = xw + d - 1;
            bool valid = rowv && ((unsigned)xx < 56u);
            int xc = min(max(xx, 0), 55);
            int q  = yc*56 + xc;
            av[d] = __ldg(&zb[(size_t)q*2]);
            cv[d] = __ldg(&zb[(size_t)q*2 + 1]);
            mk[d] = valid ? 1.f : 0.f;
        }
        if (r == 1) {  // center tap = this pixel's z
            zc[0]=av[1].x; zc[1]=av[1].y; zc[2]=av[1].z; zc[3]=av[1].w;
            zc[4]=cv[1].x; zc[5]=cv[1].y; zc[6]=cv[1].z; zc[7]=cv[1].w;
        }
        #pragma unroll
        for (int d = 0; d < 3; d++) {
            int k = r*3 + d;
            float m = mk[d];
            t[0] = fmaf(av[d].x * m, swd[0*9+k], t[0]);
            t[1] = fmaf(av[d].y * m, swd[1*9+k], t[1]);
            t[2] = fmaf(av[d].z * m, swd[2*9+k], t[2]);
            t[3] = fmaf(av[d].w * m, swd[3*9+k], t[3]);
            t[4] = fmaf(cv[d].x * m, swd[4*9+k], t[4]);
            t[5] = fmaf(cv[d].y * m, swd[5*9+k], t[5]);
            t[6] = fmaf(cv[d].z * m, swd[6*9+k], t[6]);
            t[7] = fmaf(cv[d].w * m, swd[7*9+k], t[7]);
        }
    }

    float s2z = 0.f, s2t = 0.f;
    #pragma unroll
    for (int c = 0; c < CR; c++) { s2z = fmaf(zc[c], zc[c], s2z); s2t = fmaf(t[c], t[c], s2t); }
    float iz = 1.0f / fmaxf(sqrtf(s2z), 1e-6f);
    float it = 1.0f / fmaxf(sqrtf(s2t), 1e-6f);

    float zn[CR], tn[CR];
    #pragma unroll
    for (int c = 0; c < CR; c++) { zn[c] = zc[c]*iz; tn[c] = t[c]*it; }

    float* ob = out + (size_t)b*COUT*HW + p;
    #pragma unroll
    for (int c = 0; c < CR; c++) ob[(size_t)c*HW] = zn[c];

    int k = 8;
    #pragma unroll
    for (int i = 0; i < CR; i++) {
        #pragma unroll
        for (int j = i; j < CR; j++) {
            ob[(size_t)k*HW] = zn[i]*tn[j];
            k++;
        }
    }
}

// ============================================================
extern "C" void kernel_launch(void* const* d_in, const int* in_sizes, int n_in,
                              void* d_out, int out_size) {
    const float* x     = (const float*)d_in[0];
    const float* wr    = (const float*)d_in[1];
    const float* gamma = (const float*)d_in[2];
    const float* beta  = (const float*)d_in[3];
    const float* mean  = (const float*)d_in[4];
    const float* var   = (const float*)d_in[5];
    const float* wdw   = (const float*)d_in[6];
    const float* scale = (const float*)d_in[7];
    float* out = (float*)d_out;

    conv1x1_k<<<NPAIR/PPB, 256>>>(x, wr, gamma, beta, mean, var);
    twist_k<<<NPIX/256, 256>>>(out, wdw, scale);
}

// round 5
// speedup vs baseline: 1.7917x; 1.0686x over previous
#include <cuda_runtime.h>

#define BATCH 32
#define CIN   256
#define HW    3136          // 56*56
#define HWQ   784           // HW/4
#define CR    8
#define NPIX  (BATCH*HW)    // 100352
#define NQUAD (NPIX/4)      // 25088
#define COUT  44            // 8 + 36

#define KS    4             // K-splits
#define CPK   (CIN/KS)      // 64 channels per split
#define QPB   64            // pixel-quads per block (256 thr = 64 quads * 4 splits)
#define SRSTR 18            // padded row stride (u64) for partials

// z buffer, pixel-major: [b][p][c], 32B per pixel record
__device__ float g_z[NPIX*CR];

typedef unsigned long long u64;

// ---- packed f32x2 helpers ----
__device__ __forceinline__ u64 fma2(u64 a, u64 b, u64 c) {
    u64 d;
    asm("fma.rn.f32x2 %0, %1, %2, %3;" : "=l"(d) : "l"(a), "l"(b), "l"(c));
    return d;
}
__device__ __forceinline__ u64 add2(u64 a, u64 b) {
    u64 d;
    asm("add.rn.f32x2 %0, %1, %2;" : "=l"(d) : "l"(a), "l"(b));
    return d;
}
__device__ __forceinline__ u64 pack2(float lo, float hi) {
    u64 r;
    asm("mov.b64 %0, {%1, %2};" : "=l"(r) : "f"(lo), "f"(hi));
    return r;
}
__device__ __forceinline__ float2 unpack2(u64 v) {
    float2 r;
    asm("mov.b64 {%0, %1}, %2;" : "=f"(r.x), "=f"(r.y) : "l"(v));
    return r;
}

// ============================================================
// 1x1 conv + BN(folded) + ReLU. LDG.128 (4px/thread), K-split x4,
// 2-stage pipelined loads. grid = NQUAD/QPB = 392 blocks * 256 thr
// ============================================================
__global__ void __launch_bounds__(256) conv1x1_k(const float* __restrict__ x,
                                                 const float* __restrict__ wr,
                                                 const float* __restrict__ gamma,
                                                 const float* __restrict__ beta,
                                                 const float* __restrict__ mean,
                                                 const float* __restrict__ var) {
    __shared__ u64   sw[CIN*CR];            // 16 KB folded duplicated weights
    __shared__ u64   sred[KS*QPB*SRSTR];    // 36 KB padded partials
    __shared__ float sinv[CR], sbias[CR];

    if (threadIdx.x < CR) {
        int c = threadIdx.x;
        float inv = gamma[c] * rsqrtf(var[c] + 1e-5f);
        sinv[c]  = inv;
        sbias[c] = beta[c] - mean[c] * inv;
    }
    __syncthreads();
    #pragma unroll
    for (int i = threadIdx.x; i < CIN*CR; i += 256) {
        int ci = i >> 3;
        int c  = i & 7;
        float w = wr[c*CIN + ci] * sinv[c];
        sw[i] = pack2(w, w);
    }
    __syncthreads();

    int lq = threadIdx.x & (QPB-1);      // quad within block
    int ks = threadIdx.x >> 6;           // k-split 0..3
    int qq = blockIdx.x * QPB + lq;      // global quad index, exact coverage
    int b  = qq / HWQ;
    int qi = qq % HWQ;

    const ulonglong2* xp = reinterpret_cast<const ulonglong2*>(x)
                         + (size_t)b*CIN*HWQ + (size_t)(ks*CPK)*HWQ + qi;
    const u64* swb = &sw[ks*CPK*CR];

    u64 aL[CR], aH[CR];                  // accum: px{0,1} and px{2,3}
    #pragma unroll
    for (int c = 0; c < CR; c++) { aL[c] = 0ull; aH[c] = 0ull; }

    ulonglong2 xa[4], xb[4];
    #pragma unroll
    for (int u = 0; u < 4; u++) xa[u] = xp[(size_t)u*HWQ];

    #pragma unroll 1
    for (int ci = 0; ci < CPK; ci += 8) {
        #pragma unroll
        for (int u = 0; u < 4; u++) xb[u] = xp[(size_t)(ci+4+u)*HWQ];
        #pragma unroll
        for (int u = 0; u < 4; u++) {
            const ulonglong2* wrow =
                reinterpret_cast<const ulonglong2*>(&swb[(ci+u)*CR]);
            ulonglong2 w01 = wrow[0], w23 = wrow[1], w45 = wrow[2], w67 = wrow[3];
            ulonglong2 xv = xa[u];
            aL[0]=fma2(w01.x,xv.x,aL[0]); aH[0]=fma2(w01.x,xv.y,aH[0]);
            aL[1]=fma2(w01.y,xv.x,aL[1]); aH[1]=fma2(w01.y,xv.y,aH[1]);
            aL[2]=fma2(w23.x,xv.x,aL[2]); aH[2]=fma2(w23.x,xv.y,aH[2]);
            aL[3]=fma2(w23.y,xv.x,aL[3]); aH[3]=fma2(w23.y,xv.y,aH[3]);
            aL[4]=fma2(w45.x,xv.x,aL[4]); aH[4]=fma2(w45.x,xv.y,aH[4]);
            aL[5]=fma2(w45.y,xv.x,aL[5]); aH[5]=fma2(w45.y,xv.y,aH[5]);
            aL[6]=fma2(w67.x,xv.x,aL[6]); aH[6]=fma2(w67.x,xv.y,aH[6]);
            aL[7]=fma2(w67.y,xv.x,aL[7]); aH[7]=fma2(w67.y,xv.y,aH[7]);
        }
        if (ci + 8 < CPK) {
            #pragma unroll
            for (int u = 0; u < 4; u++) xa[u] = xp[(size_t)(ci+8+u)*HWQ];
        }
        #pragma unroll
        for (int u = 0; u < 4; u++) {
            const ulonglong2* wrow =
                reinterpret_cast<const ulonglong2*>(&swb[(ci+4+u)*CR]);
            ulonglong2 w01 = wrow[0], w23 = wrow[1], w45 = wrow[2], w67 = wrow[3];
            ulonglong2 xv = xb[u];
            aL[0]=fma2(w01.x,xv.x,aL[0]); aH[0]=fma2(w01.x,xv.y,aH[0]);
            aL[1]=fma2(w01.y,xv.x,aL[1]); aH[1]=fma2(w01.y,xv.y,aH[1]);
            aL[2]=fma2(w23.x,xv.x,aL[2]); aH[2]=fma2(w23.x,xv.y,aH[2]);
            aL[3]=fma2(w23.y,xv.x,aL[3]); aH[3]=fma2(w23.y,xv.y,aH[3]);
            aL[4]=fma2(w45.x,xv.x,aL[4]); aH[4]=fma2(w45.x,xv.y,aH[4]);
            aL[5]=fma2(w45.y,xv.x,aL[5]); aH[5]=fma2(w45.y,xv.y,aH[5]);
            aL[6]=fma2(w67.x,xv.x,aL[6]); aH[6]=fma2(w67.x,xv.y,aH[6]);
            aL[7]=fma2(w67.y,xv.x,aL[7]); aH[7]=fma2(w67.y,xv.y,aH[7]);
        }
    }

    // stash 16 partials (i=c for px01, 8+c for px23), padded rows
    {
        u64* row = &sred[(size_t)(ks*QPB + lq)*SRSTR];
        ulonglong2* r2 = reinterpret_cast<ulonglong2*>(row);
        #pragma unroll
        for (int j = 0; j < 4; j++) r2[j]   = make_ulonglong2(aL[2*j], aL[2*j+1]);
        #pragma unroll
        for (int j = 0; j < 4; j++) r2[4+j] = make_ulonglong2(aH[2*j], aH[2*j+1]);
    }
    __syncthreads();

    // all 256 threads: each reduces 4 consecutive outputs of one quad
    {
        int t   = threadIdx.x;
        int lq2 = t >> 2;                 // quad handled
        int m   = t & 3;                  // which 4-output group
        int i0  = m * 4;
        int pairp = m >> 1;               // 0: px{0,1}, 1: px{2,3}
        int half  = m & 1;                // float offset 4*half, channels half*4..
        u64 s[4];
        #pragma unroll
        for (int j = 0; j < 4; j++) s[j] = 0ull;
        #pragma unroll
        for (int k = 0; k < KS; k++) {
            const ulonglong2* r2 = reinterpret_cast<const ulonglong2*>(
                &sred[(size_t)(k*QPB + lq2)*SRSTR + i0]);
            ulonglong2 p0 = r2[0], p1 = r2[1];
            s[0] = add2(s[0], p0.x); s[1] = add2(s[1], p0.y);
            s[2] = add2(s[2], p1.x); s[3] = add2(s[3], p1.y);
        }
        int qq2 = blockIdx.x * QPB + lq2;
        int b2  = qq2 / HWQ;
        int qi2 = qq2 % HWQ;
        float lo[4], hi[4];
        #pragma unroll
        for (int j = 0; j < 4; j++) {
            float2 v = unpack2(s[j]);
            float bia = sbias[half*4 + j];
            lo[j] = fmaxf(v.x + bia, 0.f);
            hi[j] = fmaxf(v.y + bia, 0.f);
        }
        int P0 = qi2*4 + pairp*2;
        float4* z0 = reinterpret_cast<float4*>(
            g_z + ((size_t)b2*HW + P0)*CR + half*4);
        float4* z1 = reinterpret_cast<float4*>(
            g_z + ((size_t)b2*HW + P0 + 1)*CR + half*4);
        *z0 = make_float4(lo[0], lo[1], lo[2], lo[3]);
        *z1 = make_float4(hi[0], hi[1], hi[2], hi[3]);
    }
}

// ============================================================
// Depthwise 3x3 (scale folded) + L2-norms + pairwise products.
// Register budget forced to <=64 via launch bounds (occupancy).
// grid = 392 blocks * 256 threads == NPIX exactly
// ============================================================
__global__ void __launch_bounds__(256, 4) twist_k(float* __restrict__ out,
                                                  const float* __restrict__ wdw,
                                                  const float* __restrict__ scale) {
    __shared__ float swd[CR*9];
    if (threadIdx.x < CR*9) swd[threadIdx.x] = wdw[threadIdx.x] * scale[threadIdx.x/9];
    __syncthreads();

    int idx = blockIdx.x * 256 + threadIdx.x;
    int b = idx / HW;
    int p = idx % HW;
    int y  = p / 56;
    int xw = p % 56;

    const float4* zb = reinterpret_cast<const float4*>(g_z) + (size_t)b*HW*2;

    float zc[CR], t[CR];
    #pragma unroll
    for (int c = 0; c < CR; c++) t[c] = 0.f;

    #pragma unroll
    for (int r = 0; r < 3; r++) {
        int yy = y + r - 1;
        bool rowv = (unsigned)yy < 56u;
        int yc = min(max(yy, 0), 55);

        float4 av[3], cv[3];
        float  mk[3];
        #pragma unroll
        for (int d = 0; d < 3; d++) {
            int xx = xw + d - 1;
            bool valid = rowv && ((unsigned)xx < 56u);
            int xc = min(max(xx, 0), 55);
            int q  = yc*56 + xc;
            av[d] = __ldg(&zb[(size_t)q*2]);
            cv[d] = __ldg(&zb[(size_t)q*2 + 1]);
            mk[d] = valid ? 1.f : 0.f;
        }
        if (r == 1) {
            zc[0]=av[1].x; zc[1]=av[1].y; zc[2]=av[1].z; zc[3]=av[1].w;
            zc[4]=cv[1].x; zc[5]=cv[1].y; zc[6]=cv[1].z; zc[7]=cv[1].w;
        }
        #pragma unroll
        for (int d = 0; d < 3; d++) {
            int k = r*3 + d;
            float m = mk[d];
            t[0] = fmaf(av[d].x * m, swd[0*9+k], t[0]);
            t[1] = fmaf(av[d].y * m, swd[1*9+k], t[1]);
            t[2] = fmaf(av[d].z * m, swd[2*9+k], t[2]);
            t[3] = fmaf(av[d].w * m, swd[3*9+k], t[3]);
            t[4] = fmaf(cv[d].x * m, swd[4*9+k], t[4]);
            t[5] = fmaf(cv[d].y * m, swd[5*9+k], t[5]);
            t[6] = fmaf(cv[d].z * m, swd[6*9+k], t[6]);
            t[7] = fmaf(cv[d].w * m, swd[7*9+k], t[7]);
        }
    }

    float s2z = 0.f, s2t = 0.f;
    #pragma unroll
    for (int c = 0; c < CR; c++) { s2z = fmaf(zc[c], zc[c], s2z); s2t = fmaf(t[c], t[c], s2t); }
    float iz = 1.0f / fmaxf(sqrtf(s2z), 1e-6f);
    float it = 1.0f / fmaxf(sqrtf(s2t), 1e-6f);

    float zn[CR], tn[CR];
    #pragma unroll
    for (int c = 0; c < CR; c++) { zn[c] = zc[c]*iz; tn[c] = t[c]*it; }

    float* ob = out + (size_t)b*COUT*HW + p;
    #pragma unroll
    for (int c = 0; c < CR; c++) ob[(size_t)c*HW] = zn[c];

    int k = 8;
    #pragma unroll
    for (int i = 0; i < CR; i++) {
        #pragma unroll
        for (int j = i; j < CR; j++) {
            ob[(size_t)k*HW] = zn[i]*tn[j];
            k++;
        }
    }
}

// ============================================================
extern "C" void kernel_launch(void* const* d_in, const int* in_sizes, int n_in,
                              void* d_out, int out_size) {
    const float* x     = (const float*)d_in[0];
    const float* wr    = (const float*)d_in[1];
    const float* gamma = (const float*)d_in[2];
    const float* beta  = (const float*)d_in[3];
    const float* mean  = (const float*)d_in[4];
    const float* var   = (const float*)d_in[5];
    const float* wdw   = (const float*)d_in[6];
    const float* scale = (const float*)d_in[7];
    float* out = (float*)d_out;

    conv1x1_k<<<NQUAD/QPB, 256>>>(x, wr, gamma, beta, mean, var);
    twist_k<<<NPIX/256, 256>>>(out, wdw, scale);
}

// round 6
// speedup vs baseline: 1.8713x; 1.0444x over previous
#include <cuda_runtime.h>
#include <cstdint>

#define BATCH 32
#define CIN   256
#define HW    3136          // 56*56
#define HWH   1568          // HW/2
#define CR    8
#define NPIX  (BATCH*HW)    // 100352
#define NPAIR (NPIX/2)      // 50176
#define COUT  44            // 8 + 36

#define KS    4             // K-splits
#define CPK   (CIN/KS)      // 64 channels per split
#define PRB   32            // pairs per block (128 thr = 32 pairs * 4 splits)
#define BPI   49            // blocks per image (1568/32)
#define NSTG  8             // channel stages (8 ch each)
#define RING  3             // cp.async ring depth
#define STGU  1024          // u64 per stage: 4ks * 8ch * 32pr

// z buffer, pixel-major: [b][p][c], 32B per pixel record
__device__ float g_z[NPIX*CR];

typedef unsigned long long u64;

__device__ __forceinline__ u64 fma2(u64 a, u64 b, u64 c) {
    u64 d;
    asm("fma.rn.f32x2 %0, %1, %2, %3;" : "=l"(d) : "l"(a), "l"(b), "l"(c));
    return d;
}
__device__ __forceinline__ u64 add2(u64 a, u64 b) {
    u64 d;
    asm("add.rn.f32x2 %0, %1, %2;" : "=l"(d) : "l"(a), "l"(b));
    return d;
}
__device__ __forceinline__ u64 pack2(float lo, float hi) {
    u64 r;
    asm("mov.b64 %0, {%1, %2};" : "=l"(r) : "f"(lo), "f"(hi));
    return r;
}
__device__ __forceinline__ float2 unpack2(u64 v) {
    float2 r;
    asm("mov.b64 {%0, %1}, %2;" : "=f"(r.x), "=f"(r.y) : "l"(v));
    return r;
}

// ============================================================
// 1x1 conv + BN(folded) + ReLU.
// 128 threads = 32 pairs x 4 K-splits, cp.async 3-stage smem ring.
// grid = 1568 blocks (49 per image, no image straddle).
// ============================================================
__global__ void __launch_bounds__(128) conv1x1_k(const float* __restrict__ x,
                                                 const float* __restrict__ wr,
                                                 const float* __restrict__ gamma,
                                                 const float* __restrict__ beta,
                                                 const float* __restrict__ mean,
                                                 const float* __restrict__ var) {
    __shared__ u64   sw[CIN*CR];        // 16 KB folded duplicated weights
    __shared__ u64   sring[RING*STGU];  // 24 KB ring; aliased as sred after loop
    __shared__ float sinv[CR], sbias[CR];

    int tid = threadIdx.x;

    if (tid < CR) {
        int c = tid;
        float inv = gamma[c] * rsqrtf(var[c] + 1e-5f);
        sinv[c]  = inv;
        sbias[c] = beta[c] - mean[c] * inv;
    }
    __syncthreads();
    #pragma unroll
    for (int i = tid; i < CIN*CR; i += 128) {
        int ci = i >> 3;
        int c  = i & 7;
        float w = wr[c*CIN + ci] * sinv[c];
        sw[i] = pack2(w, w);
    }
    __syncthreads();

    int b   = blockIdx.x / BPI;
    int ib  = blockIdx.x - b*BPI;
    int pi0 = ib * PRB;                 // first pair of this block

    int pr = tid & (PRB-1);             // pair within block
    int ks = tid >> 5;                  // k-split 0..3

    const char* xb = reinterpret_cast<const char*>(x) + (size_t)b*CIN*HWH*8;
    uint32_t ring_base = (uint32_t)__cvta_generic_to_shared(sring);

    // issue one 8-channel stage: 512 x 16B units, 4 per thread
    auto issue_stage = [&](int s, int slot) {
        #pragma unroll
        for (int j = 0; j < 4; j++) {
            int idx = tid + j*128;      // 0..511
            int ks2 = idx >> 7;
            int rem = idx & 127;
            int u   = rem >> 4;
            int prh = rem & 15;         // half-pair group (2 pairs = 16B)
            int chan = ks2*CPK + s*8 + u;
            const char* gsrc = xb + ((size_t)chan*HWH + pi0 + prh*2)*8;
            uint32_t dst = ring_base + (uint32_t)(slot*STGU + ks2*256 + u*32 + prh*2)*8;
            asm volatile("cp.async.cg.shared.global [%0], [%1], 16;\n"
                         :: "r"(dst), "l"(gsrc));
        }
        asm volatile("cp.async.commit_group;\n");
    };

    issue_stage(0, 0);
    issue_stage(1, 1);

    u64 acc[CR];
    #pragma unroll
    for (int c = 0; c < CR; c++) acc[c] = 0ull;

    #pragma unroll
    for (int s = 0; s < NSTG; s++) {
        if (s + 2 < NSTG) issue_stage(s + 2, (s + 2) % RING);
        else              asm volatile("cp.async.commit_group;\n");  // empty group
        asm volatile("cp.async.wait_group 2;\n");
        __syncthreads();                 // stage s visible block-wide

        const u64* st = &sring[(s % RING)*STGU + ks*256];
        #pragma unroll
        for (int u = 0; u < 8; u++) {
            u64 xv = st[u*32 + pr];
            const ulonglong2* wrow =
                reinterpret_cast<const ulonglong2*>(&sw[(ks*CPK + s*8 + u)*CR]);
            ulonglong2 w01 = wrow[0], w23 = wrow[1], w45 = wrow[2], w67 = wrow[3];
            acc[0] = fma2(w01.x, xv, acc[0]);
            acc[1] = fma2(w01.y, xv, acc[1]);
            acc[2] = fma2(w23.x, xv, acc[2]);
            acc[3] = fma2(w23.y, xv, acc[3]);
            acc[4] = fma2(w45.x, xv, acc[4]);
            acc[5] = fma2(w45.y, xv, acc[5]);
            acc[6] = fma2(w67.x, xv, acc[6]);
            acc[7] = fma2(w67.y, xv, acc[7]);
        }
        __syncthreads();                 // done reading slot before reuse
    }

    asm volatile("cp.async.wait_group 0;\n");
    __syncthreads();

    // partials into aliased ring: row stride 9 u64
    u64* sred = sring;
    {
        u64* row = &sred[(size_t)(ks*PRB + pr)*9];
        #pragma unroll
        for (int c = 0; c < CR; c++) row[c] = acc[c];
    }
    __syncthreads();

    // reduce: thread t -> pair pr2, channels {2g, 2g+1}
    {
        int pr2 = tid >> 2;
        int g   = tid & 3;
        u64 s0 = 0ull, s1 = 0ull;
        #pragma unroll
        for (int k = 0; k < KS; k++) {
            const u64* row = &sred[(size_t)(k*PRB + pr2)*9 + 2*g];
            s0 = add2(s0, row[0]);
            s1 = add2(s1, row[1]);
        }
        float2 v0 = unpack2(s0);         // channel 2g   : (px0, px1)
        float2 v1 = unpack2(s1);         // channel 2g+1 : (px0, px1)
        float b0 = sbias[2*g], b1 = sbias[2*g+1];
        float a0 = fmaxf(v0.x + b0, 0.f), a1 = fmaxf(v1.x + b1, 0.f);
        float c0 = fmaxf(v0.y + b0, 0.f), c1 = fmaxf(v1.y + b1, 0.f);
        int pi2 = pi0 + pr2;
        int px0 = 2*pi2;
        float2* z0 = reinterpret_cast<float2*>(g_z + ((size_t)b*HW + px0)*CR + 2*g);
        float2* z1 = reinterpret_cast<float2*>(g_z + ((size_t)b*HW + px0 + 1)*CR + 2*g);
        *z0 = make_float2(a0, a1);
        *z1 = make_float2(c0, c1);
    }
}

// ============================================================
// Depthwise 3x3 (scale folded) + L2-norms + pairwise products.
// smem tile: 6 rows x 56 cols (zero-filled y-halo), 1 px/thread.
// grid = 32 images x 14 bands = 448 blocks of 224 threads.
// ============================================================
__global__ void __launch_bounds__(224) twist_k(float* __restrict__ out,
                                               const float* __restrict__ wdw,
                                               const float* __restrict__ scale) {
    __shared__ float4 s4[6*56*2];       // 10.5 KB tile
    __shared__ float  swd[CR*9];

    int tid = threadIdx.x;
    if (tid < CR*9) swd[tid] = wdw[tid] * scale[tid/9];

    int b    = blockIdx.x / 14;
    int band = blockIdx.x - b*14;
    int y0   = band * 4;

    const float4* zb = reinterpret_cast<const float4*>(g_z) + (size_t)b*HW*2;

    // cooperative tile load: 672 float4 = 3 per thread
    #pragma unroll
    for (int j = 0; j < 3; j++) {
        int f   = tid + j*224;          // 0..671
        int r   = f / 112;
        int rem = f - r*112;
        int col = rem >> 1;
        int h   = rem & 1;
        int gy  = y0 + r - 1;
        float4 v = make_float4(0.f, 0.f, 0.f, 0.f);
        if ((unsigned)gy < 56u)
            v = __ldg(&zb[(size_t)(gy*56 + col)*2 + h]);
        s4[f] = v;
    }
    __syncthreads();

    int row = tid / 56;                 // 0..3
    int col = tid - row*56;             // 0..55
    int sr  = row + 1;                  // smem row 1..4

    float zc[CR], t[CR];
    {
        float4 a = s4[(sr*56 + col)*2];
        float4 c = s4[(sr*56 + col)*2 + 1];
        zc[0]=a.x; zc[1]=a.y; zc[2]=a.z; zc[3]=a.w;
        zc[4]=c.x; zc[5]=c.y; zc[6]=c.z; zc[7]=c.w;
    }
    #pragma unroll
    for (int c = 0; c < CR; c++) t[c] = 0.f;

    #pragma unroll
    for (int dy = -1; dy <= 1; dy++) {
        int srow = sr + dy;
        #pragma unroll
        for (int dx = -1; dx <= 1; dx++) {
            int cc = col + dx;
            bool valid = (unsigned)cc < 56u;
            int qc = min(max(cc, 0), 55);
            float m = valid ? 1.f : 0.f;
            float4 a = s4[(srow*56 + qc)*2];
            float4 c = s4[(srow*56 + qc)*2 + 1];
            int k = (dy+1)*3 + (dx+1);
            t[0] = fmaf(a.x * m, swd[0*9+k], t[0]);
            t[1] = fmaf(a.y * m, swd[1*9+k], t[1]);
            t[2] = fmaf(a.z * m, swd[2*9+k], t[2]);
            t[3] = fmaf(a.w * m, swd[3*9+k], t[3]);
            t[4] = fmaf(c.x * m, swd[4*9+k], t[4]);
            t[5] = fmaf(c.y * m, swd[5*9+k], t[5]);
            t[6] = fmaf(c.z * m, swd[6*9+k], t[6]);
            t[7] = fmaf(c.w * m, swd[7*9+k], t[7]);
        }
    }

    float s2z = 0.f, s2t = 0.f;
    #pragma unroll
    for (int c = 0; c < CR; c++) { s2z = fmaf(zc[c], zc[c], s2z); s2t = fmaf(t[c], t[c], s2t); }
    float iz = 1.0f / fmaxf(sqrtf(s2z), 1e-6f);
    float it = 1.0f / fmaxf(sqrtf(s2t), 1e-6f);

    float zn[CR], tn[CR];
    #pragma unroll
    for (int c = 0; c < CR; c++) { zn[c] = zc[c]*iz; tn[c] = t[c]*it; }

    int p = (y0 + row)*56 + col;
    float* ob = out + (size_t)b*COUT*HW + p;
    #pragma unroll
    for (int c = 0; c < CR; c++) ob[(size_t)c*HW] = zn[c];

    int k = 8;
    #pragma unroll
    for (int i = 0; i < CR; i++) {
        #pragma unroll
        for (int j = i; j < CR; j++) {
            ob[(size_t)k*HW] = zn[i]*tn[j];
            k++;
        }
    }
}

// ============================================================
extern "C" void kernel_launch(void* const* d_in, const int* in_sizes, int n_in,
                              void* d_out, int out_size) {
    const float* x     = (const float*)d_in[0];
    const float* wr    = (const float*)d_in[1];
    const float* gamma = (const float*)d_in[2];
    const float* beta  = (const float*)d_in[3];
    const float* mean  = (const float*)d_in[4];
    const float* var   = (const float*)d_in[5];
    const float* wdw   = (const float*)d_in[6];
    const float* scale = (const float*)d_in[7];
    float* out = (float*)d_out;

    conv1x1_k<<<BATCH*BPI, 128>>>(x, wr, gamma, beta, mean, var);
    twist_k<<<BATCH*14, 224>>>(out, wdw, scale);
}

// round 7
// speedup vs baseline: 1.8867x; 1.0082x over previous
#include <cuda_runtime.h>
#include <cstdint>

#define BATCH 32
#define CIN   256
#define HW    3136          // 56*56
#define HWH   1568          // HW/2
#define CR    8
#define NPIX  (BATCH*HW)    // 100352
#define COUT  44            // 8 + 36

#define KS    4             // K-splits (= warps per block)
#define CPK   (CIN/KS)      // 64 channels per split
#define PRB   32            // pairs per block (one warp's lanes)
#define BPI   49            // blocks per image (1568/32)
#define NSTG  8             // channel stages (8 ch each)
#define RING  3             // per-warp cp.async ring depth
#define WSTG  256           // u64 per warp-stage: 8ch * 32pr

// z buffer, pixel-major: [b][p][c], 32B per pixel record
__device__ float g_z[NPIX*CR];

typedef unsigned long long u64;

__device__ __forceinline__ u64 fma2(u64 a, u64 b, u64 c) {
    u64 d;
    asm("fma.rn.f32x2 %0, %1, %2, %3;" : "=l"(d) : "l"(a), "l"(b), "l"(c));
    return d;
}
__device__ __forceinline__ u64 add2(u64 a, u64 b) {
    u64 d;
    asm("add.rn.f32x2 %0, %1, %2;" : "=l"(d) : "l"(a), "l"(b));
    return d;
}
__device__ __forceinline__ u64 pack2(float lo, float hi) {
    u64 r;
    asm("mov.b64 %0, {%1, %2};" : "=l"(r) : "f"(lo), "f"(hi));
    return r;
}
__device__ __forceinline__ float2 unpack2(u64 v) {
    float2 r;
    asm("mov.b64 {%0, %1}, %2;" : "=f"(r.x), "=f"(r.y) : "l"(v));
    return r;
}

// ============================================================
// 1x1 conv + BN(folded) + ReLU.
// 128 threads = 4 warps; warp w owns K-split w for 32 pairs.
// Per-warp cp.async ring, NO block barriers in mainloop.
// grid = 1568 blocks (49 per image).
// ============================================================
__global__ void __launch_bounds__(128) conv1x1_k(const float* __restrict__ x,
                                                 const float* __restrict__ wr,
                                                 const float* __restrict__ gamma,
                                                 const float* __restrict__ beta,
                                                 const float* __restrict__ mean,
                                                 const float* __restrict__ var) {
    __shared__ __align__(16) u64 sw[CIN*CR];            // 16 KB weights
    __shared__ __align__(16) u64 sring[KS*RING*WSTG];   // 24 KB per-warp rings
    __shared__ float sinv[CR], sbias[CR];

    int tid  = threadIdx.x;
    int w    = tid >> 5;                 // warp id = K-split
    int lane = tid & 31;

    if (tid < CR) {
        int c = tid;
        float inv = gamma[c] * rsqrtf(var[c] + 1e-5f);
        sinv[c]  = inv;
        sbias[c] = beta[c] - mean[c] * inv;
    }
    __syncthreads();
    #pragma unroll
    for (int i = tid; i < CIN*CR; i += 128) {
        int ci = i >> 3;
        int c  = i & 7;
        float wgt = wr[c*CIN + ci] * sinv[c];
        sw[i] = pack2(wgt, wgt);
    }
    __syncthreads();

    int b   = blockIdx.x / BPI;
    int ib  = blockIdx.x - b*BPI;
    int pi0 = ib * PRB;                  // first pair of this block

    const char* xb = reinterpret_cast<const char*>(x) + (size_t)b*CIN*HWH*8;
    uint32_t ring_base = (uint32_t)__cvta_generic_to_shared(sring);

    // one warp-stage: 128 x 16B units, 4 per lane
    auto issue_stage = [&](int s, int slot) {
        #pragma unroll
        for (int j = 0; j < 4; j++) {
            int idx = lane + j*32;       // 0..127
            int u   = idx >> 4;          // channel within stage
            int prh = idx & 15;          // 2-pair group
            int chan = w*CPK + s*8 + u;
            const char* gsrc = xb + ((size_t)chan*HWH + pi0 + prh*2)*8;
            uint32_t dst = ring_base
                + (uint32_t)((w*RING + slot)*WSTG + u*32 + prh*2)*8;
            asm volatile("cp.async.cg.shared.global [%0], [%1], 16;\n"
                         :: "r"(dst), "l"(gsrc));
        }
        asm volatile("cp.async.commit_group;\n");
    };

    issue_stage(0, 0);
    issue_stage(1, 1);

    u64 acc[CR];
    #pragma unroll
    for (int c = 0; c < CR; c++) acc[c] = 0ull;

    #pragma unroll
    for (int s = 0; s < NSTG; s++) {
        if (s + 2 < NSTG) issue_stage(s + 2, (s + 2) % RING);
        else              asm volatile("cp.async.commit_group;\n");
        asm volatile("cp.async.wait_group 2;\n");
        __syncwarp();                    // stage s visible warp-wide

        const u64* st = &sring[(w*RING + (s % RING))*WSTG];
        #pragma unroll
        for (int u = 0; u < 8; u++) {
            u64 xv = st[u*32 + lane];
            const ulonglong2* wrow =
                reinterpret_cast<const ulonglong2*>(&sw[(w*CPK + s*8 + u)*CR]);
            ulonglong2 w01 = wrow[0], w23 = wrow[1], w45 = wrow[2], w67 = wrow[3];
            acc[0] = fma2(w01.x, xv, acc[0]);
            acc[1] = fma2(w01.y, xv, acc[1]);
            acc[2] = fma2(w23.x, xv, acc[2]);
            acc[3] = fma2(w23.y, xv, acc[3]);
            acc[4] = fma2(w45.x, xv, acc[4]);
            acc[5] = fma2(w45.y, xv, acc[5]);
            acc[6] = fma2(w67.x, xv, acc[6]);
            acc[7] = fma2(w67.y, xv, acc[7]);
        }
        __syncwarp();                    // reads done before slot reuse
    }
    asm volatile("cp.async.wait_group 0;\n");
    __syncthreads();                     // all warps out of ring

    // partials into aliased ring: row stride 9 u64
    u64* sred = sring;
    {
        u64* row = &sred[(size_t)(w*PRB + lane)*9];
        #pragma unroll
        for (int c = 0; c < CR; c++) row[c] = acc[c];
    }
    __syncthreads();

    // reduce: thread t -> pair pr2, channels {2g, 2g+1}
    {
        int pr2 = tid >> 2;
        int g   = tid & 3;
        u64 s0 = 0ull, s1 = 0ull;
        #pragma unroll
        for (int k = 0; k < KS; k++) {
            const u64* row = &sred[(size_t)(k*PRB + pr2)*9 + 2*g];
            s0 = add2(s0, row[0]);
            s1 = add2(s1, row[1]);
        }
        float2 v0 = unpack2(s0);
        float2 v1 = unpack2(s1);
        float b0 = sbias[2*g], b1 = sbias[2*g+1];
        float a0 = fmaxf(v0.x + b0, 0.f), a1 = fmaxf(v1.x + b1, 0.f);
        float c0 = fmaxf(v0.y + b0, 0.f), c1 = fmaxf(v1.y + b1, 0.f);
        int px0 = 2*(pi0 + pr2);
        float2* z0 = reinterpret_cast<float2*>(g_z + ((size_t)b*HW + px0)*CR + 2*g);
        float2* z1 = reinterpret_cast<float2*>(g_z + ((size_t)b*HW + px0 + 1)*CR + 2*g);
        *z0 = make_float2(a0, a1);
        *z1 = make_float2(c0, c1);
    }
}

// ============================================================
// Depthwise 3x3 (scale folded) + L2-norms + pairwise products.
// Fully halo-padded split planes: sA/sC[6][58], zero borders ->
// taps are unconditional LDS.128 + pure FMA (no masks/clamps).
// grid = 32 images x 14 bands = 448 blocks of 224 threads.
// ============================================================
#define TW 58
__global__ void __launch_bounds__(224) twist_k(float* __restrict__ out,
                                               const float* __restrict__ wdw,
                                               const float* __restrict__ scale) {
    __shared__ float4 sA[6*TW];         // 5.4 KB  (channels 0-3)
    __shared__ float4 sC[6*TW];         // 5.4 KB  (channels 4-7)
    __shared__ float  swd[CR*9];

    int tid = threadIdx.x;
    if (tid < CR*9) swd[tid] = wdw[tid] * scale[tid/9];

    int b    = blockIdx.x / 14;
    int band = blockIdx.x - b*14;
    int y0   = band * 4;

    const float4* zb = reinterpret_cast<const float4*>(g_z) + (size_t)b*HW*2;

    // cooperative halo-padded tile load: 348 entries per plane
    for (int f = tid; f < 6*TW; f += 224) {
        int r  = f / TW;
        int c  = f - r*TW;
        int gy = y0 + r - 1;
        int gx = c - 1;
        float4 va = make_float4(0.f,0.f,0.f,0.f);
        float4 vc = va;
        if ((unsigned)gy < 56u && (unsigned)gx < 56u) {
            size_t q = (size_t)(gy*56 + gx)*2;
            va = __ldg(&zb[q]);
            vc = __ldg(&zb[q+1]);
        }
        sA[f] = va;
        sC[f] = vc;
    }
    __syncthreads();

    int row = tid / 56;                 // 0..3
    int col = tid - row*56;             // 0..55
    int s0  = (row+1)*TW + (col+1);     // center index

    float zc[CR], t[CR];
    {
        float4 a = sA[s0];
        float4 c = sC[s0];
        zc[0]=a.x; zc[1]=a.y; zc[2]=a.z; zc[3]=a.w;
        zc[4]=c.x; zc[5]=c.y; zc[6]=c.z; zc[7]=c.w;
    }
    #pragma unroll
    for (int c = 0; c < CR; c++) t[c] = 0.f;

    #pragma unroll
    for (int dy = -1; dy <= 1; dy++) {
        #pragma unroll
        for (int dx = -1; dx <= 1; dx++) {
            int si = s0 + dy*TW + dx;
            int k  = (dy+1)*3 + (dx+1);
            float4 a = sA[si];
            float4 c = sC[si];
            t[0] = fmaf(a.x, swd[0*9+k], t[0]);
            t[1] = fmaf(a.y, swd[1*9+k], t[1]);
            t[2] = fmaf(a.z, swd[2*9+k], t[2]);
            t[3] = fmaf(a.w, swd[3*9+k], t[3]);
            t[4] = fmaf(c.x, swd[4*9+k], t[4]);
            t[5] = fmaf(c.y, swd[5*9+k], t[5]);
            t[6] = fmaf(c.z, swd[6*9+k], t[6]);
            t[7] = fmaf(c.w, swd[7*9+k], t[7]);
        }
    }

    float s2z = 0.f, s2t = 0.f;
    #pragma unroll
    for (int c = 0; c < CR; c++) { s2z = fmaf(zc[c], zc[c], s2z); s2t = fmaf(t[c], t[c], s2t); }
    float iz = 1.0f / fmaxf(sqrtf(s2z), 1e-6f);
    float it = 1.0f / fmaxf(sqrtf(s2t), 1e-6f);

    float zn[CR], tn[CR];
    #pragma unroll
    for (int c = 0; c < CR; c++) { zn[c] = zc[c]*iz; tn[c] = t[c]*it; }

    int p = (y0 + row)*56 + col;
    float* ob = out + (size_t)b*COUT*HW + p;
    #pragma unroll
    for (int c = 0; c < CR; c++) ob[(size_t)c*HW] = zn[c];

    int k = 8;
    #pragma unroll
    for (int i = 0; i < CR; i++) {
        #pragma unroll
        for (int j = i; j < CR; j++) {
            ob[(size_t)k*HW] = zn[i]*tn[j];
            k++;
        }
    }
}

// ============================================================
extern "C" void kernel_launch(void* const* d_in, const int* in_sizes, int n_in,
                              void* d_out, int out_size) {
    const float* x     = (const float*)d_in[0];
    const float* wr    = (const float*)d_in[1];
    const float* gamma = (const float*)d_in[2];
    const float* beta  = (const float*)d_in[3];
    const float* mean  = (const float*)d_in[4];
    const float* var   = (const float*)d_in[5];
    const float* wdw   = (const float*)d_in[6];
    const float* scale = (const float*)d_in[7];
    float* out = (float*)d_out;

    conv1x1_k<<<BATCH*BPI, 128>>>(x, wr, gamma, beta, mean, var);
    twist_k<<<BATCH*14, 224>>>(out, wdw, scale);
}